// round 13
// baseline (speedup 1.0000x reference)
#include <cuda_runtime.h>
#include <cuda_bf16.h>
#include <cstdint>
#include <math.h>

#define SEQ 4096
#define DIM 1024
#define NH  16
#define HD  64

// ---------------------------------------------------------------------------
// Scratch (allocation-free rule: __device__ globals)
// ---------------------------------------------------------------------------
// int8 two-term fixed point (projection inputs)
__device__ __align__(16) char g_x1[SEQ * DIM],  g_x0[SEQ * DIM];
__device__ __align__(16) char g_Wq1[DIM * DIM], g_Wq0[DIM * DIM];
__device__ __align__(16) char g_Wk1[DIM * DIM], g_Wk0[DIM * DIM];
__device__ __align__(16) char g_Wv1[DIM * DIM], g_Wv0[DIM * DIM];
// bf16 split (attention + out path, identical to round-9 layout)
__device__ __align__(16) __nv_bfloat16 g_Qh[SEQ * DIM],  g_Ql[SEQ * DIM];   // pre-scaled 0.125
__device__ __align__(16) __nv_bfloat16 g_Kh[SEQ * DIM],  g_Kl[SEQ * DIM];
__device__ __align__(16) __nv_bfloat16 g_Vth[DIM * SEQ], g_Vtl[DIM * SEQ];  // transposed [dim][seq]
__device__ __align__(16) __nv_bfloat16 g_ch[SEQ * DIM],  g_cl[SEQ * DIM];
__device__ __align__(16) __nv_bfloat16 g_Woh[DIM * DIM], g_Wol[DIM * DIM];

// quantization scales (distribution-derived, conservative)
#define SX_MAX 6.5f
#define SW_MAX 0.125f
#define DEQ ((SX_MAX / 127.0f) * (SW_MAX / 127.0f))

// ---------------------------------------------------------------------------
// PTX helpers (baseline PTX only — compute_103-safe)
// ---------------------------------------------------------------------------
__device__ __forceinline__ uint32_t smem_u32(const void* p) {
    uint32_t a;
    asm("{ .reg .u64 t; cvta.to.shared.u64 t, %1; cvt.u32.u64 %0, t; }"
        : "=r"(a) : "l"(p));
    return a;
}
#define CP_ASYNC16(dst, src) \
    asm volatile("cp.async.ca.shared.global [%0], [%1], 16;" \
                 :: "r"(dst), "l"(src) : "memory")
#define CP_COMMIT()  asm volatile("cp.async.commit_group;" ::: "memory")
#define CP_WAIT1()   asm volatile("cp.async.wait_group 1;" ::: "memory")
#define CP_WAIT0()   asm volatile("cp.async.wait_group 0;" ::: "memory")

__device__ __forceinline__ void mma16816(float* c,
                                         uint32_t a0, uint32_t a1, uint32_t a2, uint32_t a3,
                                         uint32_t b0, uint32_t b1) {
    asm volatile(
        "mma.sync.aligned.m16n8k16.row.col.f32.bf16.bf16.f32 "
        "{%0,%1,%2,%3}, {%4,%5,%6,%7}, {%8,%9}, {%0,%1,%2,%3};"
        : "+f"(c[0]), "+f"(c[1]), "+f"(c[2]), "+f"(c[3])
        : "r"(a0), "r"(a1), "r"(a2), "r"(a3), "r"(b0), "r"(b1));
}
__device__ __forceinline__ void imma16832(int* c,
                                          uint32_t a0, uint32_t a1, uint32_t a2, uint32_t a3,
                                          uint32_t b0, uint32_t b1) {
    asm volatile(
        "mma.sync.aligned.m16n8k32.row.col.s32.s8.s8.s32 "
        "{%0,%1,%2,%3}, {%4,%5,%6,%7}, {%8,%9}, {%0,%1,%2,%3};"
        : "+r"(c[0]), "+r"(c[1]), "+r"(c[2]), "+r"(c[3])
        : "r"(a0), "r"(a1), "r"(a2), "r"(a3), "r"(b0), "r"(b1));
}

__device__ __forceinline__ void split2(float v0, float v1, uint32_t& hi, uint32_t& lo) {
    __nv_bfloat16 h0 = __float2bfloat16(v0), h1 = __float2bfloat16(v1);
    __nv_bfloat16 l0 = __float2bfloat16(v0 - __bfloat162float(h0));
    __nv_bfloat16 l1 = __float2bfloat16(v1 - __bfloat162float(h1));
    hi = ((uint32_t)__bfloat16_as_ushort(h1) << 16) | __bfloat16_as_ushort(h0);
    lo = ((uint32_t)__bfloat16_as_ushort(l1) << 16) | __bfloat16_as_ushort(l0);
}

// ---------------------------------------------------------------------------
// Converters
// ---------------------------------------------------------------------------
// fp32 -> two-term int8: v ~= s*(q1 + q0/128)
__global__ __launch_bounds__(256) void convert_i8_kernel(const float* __restrict__ src,
                                                         int sel, int rows, float inv_s)
{
    char *d1, *d0;
    switch (sel) {
        case 0: d1 = g_x1;  d0 = g_x0;  break;
        case 1: d1 = g_Wq1; d0 = g_Wq0; break;
        case 2: d1 = g_Wk1; d0 = g_Wk0; break;
        default: d1 = g_Wv1; d0 = g_Wv0; break;
    }
    int id = blockIdx.x * 256 + threadIdx.x;
    int r = id >> 7;
    if (r >= rows) return;
    int c = (id & 127) << 3;
    size_t off = (size_t)r * DIM + c;

    float4 v0 = *(const float4*)&src[off];
    float4 v1 = *(const float4*)&src[off + 4];
    float v[8] = {v0.x, v0.y, v0.z, v0.w, v1.x, v1.y, v1.z, v1.w};

    union { uint2 u; char b[8]; } P1, P0;
#pragma unroll
    for (int i = 0; i < 8; i++) {
        float q = fminf(fmaxf(v[i] * inv_s, -127.0f), 127.0f);
        float q1 = rintf(q);
        float q0 = rintf((q - q1) * 128.0f);
        P1.b[i] = (char)(int)q1;
        P0.b[i] = (char)(int)q0;
    }
    *(uint2*)&d1[off] = P1.u;
    *(uint2*)&d0[off] = P0.u;
}

// fp32 -> bf16 split (Wo only)
__global__ __launch_bounds__(256) void convert_bf16_kernel(const float* __restrict__ src)
{
    int id = blockIdx.x * 256 + threadIdx.x;
    int r = id >> 7;
    if (r >= DIM) return;
    int c = (id & 127) << 3;
    size_t off = (size_t)r * DIM + c;

    float4 v0 = *(const float4*)&src[off];
    float4 v1 = *(const float4*)&src[off + 4];
    float v[8] = {v0.x, v0.y, v0.z, v0.w, v1.x, v1.y, v1.z, v1.w};
    union { uint4 u; __nv_bfloat16 b[8]; } H, L;
#pragma unroll
    for (int i = 0; i < 8; i++) {
        __nv_bfloat16 h = __float2bfloat16(v[i]);
        H.b[i] = h;
        L.b[i] = __float2bfloat16(v[i] - __bfloat162float(h));
    }
    *(uint4*)&g_Woh[off] = H.u;
    *(uint4*)&g_Wol[off] = L.u;
}

// ---------------------------------------------------------------------------
// int8 IMMA GEMM (QKV projections): C = sx*sw*(A1B1 + (A1B0 + A0B1)/128).
// CTA 128x128, k-chunk 32 (one IMMA k-step), cp.async double-buffered.
// smem row stride 48B (conflict-free 4B frag loads). Epilogues:
//  z=0: Q split-bf16 row-major *0.125; z=1: K split-bf16; z=2: V split-bf16 transposed.
// ---------------------------------------------------------------------------
#define QSTRIDE   48
#define QMAT      (128 * QSTRIDE)             // 6144
#define STAGE_I   (4 * QMAT)                  // 24576 (A1,A0,B1,B0)
#define MM_SMEM_I (2 * STAGE_I)               // 49152

__global__ __launch_bounds__(256) void mm_qkv_i8_kernel()
{
    const char *B1, *B0;
    __nv_bfloat16 *Dh, *Dl;
    if (blockIdx.z == 0)      { B1 = g_Wq1; B0 = g_Wq0; Dh = g_Qh; Dl = g_Ql; }
    else if (blockIdx.z == 1) { B1 = g_Wk1; B0 = g_Wk0; Dh = g_Kh; Dl = g_Kl; }
    else                      { B1 = g_Wv1; B0 = g_Wv0; Dh = g_Vth; Dl = g_Vtl; }
    const float dq = DEQ * ((blockIdx.z == 0) ? 0.125f : 1.0f);

    extern __shared__ char smem[];
    const uint32_t sb = smem_u32(smem);
    const int tid  = threadIdx.x;
    const int wid  = tid >> 5;
    const int lane = tid & 31;
    const int wm   = wid & 1;
    const int wn   = wid >> 1;
    const int mb   = blockIdx.y;
    const int nb   = blockIdx.x;
    const int r4   = lane >> 2;
    const int kq   = (lane & 3) * 2;
    const int kq4  = (lane & 3) * 4;

    int accA[4][4][4], accM[4][4][4];
#pragma unroll
    for (int fm = 0; fm < 4; fm++)
#pragma unroll
        for (int fn = 0; fn < 4; fn++)
#pragma unroll
            for (int q = 0; q < 4; q++) { accA[fm][fn][q] = 0; accM[fm][fn][q] = 0; }

    auto load_chunk = [&](int stage, int ch) {
        const uint32_t st = sb + stage * STAGE_I;
        int r = tid >> 1, sec = tid & 1;
        uint32_t d = st + r * QSTRIDE + sec * 16;
        size_t ga = (size_t)(mb * 128 + r) * DIM + ch * 32 + sec * 16;
        size_t gb = (size_t)(nb * 128 + r) * DIM + ch * 32 + sec * 16;
        CP_ASYNC16(d,            g_x1 + ga);
        CP_ASYNC16(d + QMAT,     g_x0 + ga);
        CP_ASYNC16(d + 2 * QMAT, B1 + gb);
        CP_ASYNC16(d + 3 * QMAT, B0 + gb);
    };

    load_chunk(0, 0);
    CP_COMMIT();

#pragma unroll 1
    for (int ch = 0; ch < 32; ch++) {
        if (ch + 1 < 32) { load_chunk((ch + 1) & 1, ch + 1); CP_COMMIT(); CP_WAIT1(); }
        else             { CP_WAIT0(); }
        __syncthreads();

        const char* stg = smem + (ch & 1) * STAGE_I;
        const char* aB  = stg + (wm * 64) * QSTRIDE;
        const char* bB  = stg + 2 * QMAT + (wn * 32) * QSTRIDE;

        uint32_t b1r[4][2], b0r[4][2];
#pragma unroll
        for (int fn = 0; fn < 4; fn++) {
            const char* p = bB + (fn * 8 + r4) * QSTRIDE + kq4;
            b1r[fn][0] = *(const uint32_t*)p;
            b1r[fn][1] = *(const uint32_t*)(p + 16);
            b0r[fn][0] = *(const uint32_t*)(p + QMAT);
            b0r[fn][1] = *(const uint32_t*)(p + QMAT + 16);
        }
#pragma unroll
        for (int fm = 0; fm < 4; fm++) {
            const char* p = aB + (fm * 16 + r4) * QSTRIDE + kq4;
            uint32_t a10 = *(const uint32_t*)p;
            uint32_t a11 = *(const uint32_t*)(p + 8 * QSTRIDE);
            uint32_t a12 = *(const uint32_t*)(p + 16);
            uint32_t a13 = *(const uint32_t*)(p + 8 * QSTRIDE + 16);
            uint32_t a00 = *(const uint32_t*)(p + QMAT);
            uint32_t a01 = *(const uint32_t*)(p + QMAT + 8 * QSTRIDE);
            uint32_t a02 = *(const uint32_t*)(p + QMAT + 16);
            uint32_t a03 = *(const uint32_t*)(p + QMAT + 8 * QSTRIDE + 16);
#pragma unroll
            for (int fn = 0; fn < 4; fn++) {
                imma16832(accA[fm][fn], a10, a11, a12, a13, b1r[fn][0], b1r[fn][1]);
                imma16832(accM[fm][fn], a10, a11, a12, a13, b0r[fn][0], b0r[fn][1]);
                imma16832(accM[fm][fn], a00, a01, a02, a03, b1r[fn][0], b1r[fn][1]);
            }
        }
        __syncthreads();
    }

    // epilogue: dequant + split-bf16 stores
#pragma unroll
    for (int fm = 0; fm < 4; fm++) {
        const int row = mb * 128 + wm * 64 + fm * 16 + r4;
#pragma unroll
        for (int fn = 0; fn < 4; fn++) {
            const int col = nb * 128 + wn * 32 + fn * 8 + kq;
            float v0 = ((float)accA[fm][fn][0] + (float)accM[fm][fn][0] * 0.0078125f) * dq;
            float v1 = ((float)accA[fm][fn][1] + (float)accM[fm][fn][1] * 0.0078125f) * dq;
            float v2 = ((float)accA[fm][fn][2] + (float)accM[fm][fn][2] * 0.0078125f) * dq;
            float v3 = ((float)accA[fm][fn][3] + (float)accM[fm][fn][3] * 0.0078125f) * dq;
            if (blockIdx.z < 2) {
                uint32_t hi, lo;
                split2(v0, v1, hi, lo);
                *(uint32_t*)&Dh[(size_t)row * DIM + col] = hi;
                *(uint32_t*)&Dl[(size_t)row * DIM + col] = lo;
                split2(v2, v3, hi, lo);
                *(uint32_t*)&Dh[(size_t)(row + 8) * DIM + col] = hi;
                *(uint32_t*)&Dl[(size_t)(row + 8) * DIM + col] = lo;
            } else {
                __nv_bfloat16 h, l;
                h = __float2bfloat16(v0); l = __float2bfloat16(v0 - __bfloat162float(h));
                Dh[(size_t)col * SEQ + row] = h;       Dl[(size_t)col * SEQ + row] = l;
                h = __float2bfloat16(v1); l = __float2bfloat16(v1 - __bfloat162float(h));
                Dh[(size_t)(col + 1) * SEQ + row] = h; Dl[(size_t)(col + 1) * SEQ + row] = l;
                h = __float2bfloat16(v2); l = __float2bfloat16(v2 - __bfloat162float(h));
                Dh[(size_t)col * SEQ + row + 8] = h;   Dl[(size_t)col * SEQ + row + 8] = l;
                h = __float2bfloat16(v3); l = __float2bfloat16(v3 - __bfloat162float(h));
                Dh[(size_t)(col + 1) * SEQ + row + 8] = h; Dl[(size_t)(col + 1) * SEQ + row + 8] = l;
            }
        }
    }
}

// ---------------------------------------------------------------------------
// bf16 3-term GEMM for the output projection (round-9 verbatim, mode-0 only)
// ---------------------------------------------------------------------------
#define MAT_BYTES   (128 * 40 * 2)            // 10240
#define STAGE_B4    (4 * MAT_BYTES)           // 40960
#define MM_SMEM_B   (2 * STAGE_B4)            // 81920

__global__ __launch_bounds__(256) void mm_out_kernel(const float* __restrict__ bias,
                                                     float* __restrict__ Cf)
{
    const __nv_bfloat16* Ah = g_ch; const __nv_bfloat16* Al = g_cl;
    const __nv_bfloat16* Bh = g_Woh; const __nv_bfloat16* Bl = g_Wol;

    extern __shared__ char smem[];
    const uint32_t sb = smem_u32(smem);
    const int tid  = threadIdx.x;
    const int wid  = tid >> 5;
    const int lane = tid & 31;
    const int wm   = wid & 1;
    const int wn   = wid >> 1;
    const int mb   = blockIdx.y;
    const int nb   = blockIdx.x;
    const int r4 = lane >> 2;
    const int kq = (lane & 3) * 2;

    float acc[4][4][4];
#pragma unroll
    for (int fm = 0; fm < 4; fm++)
#pragma unroll
        for (int fn = 0; fn < 4; fn++)
#pragma unroll
            for (int q = 0; q < 4; q++) acc[fm][fn][q] = 0.0f;

    auto load_chunk = [&](int stage, int ch) {
        const uint32_t st = sb + stage * STAGE_B4;
#pragma unroll
        for (int it = 0; it < 2; it++) {
            int i = tid + it * 256;
            int r = i >> 2, sec = i & 3;
            uint32_t d = st + r * 80 + sec * 16;
            size_t ga = (size_t)(mb * 128 + r) * DIM + ch * 32 + sec * 8;
            size_t gb = (size_t)(nb * 128 + r) * DIM + ch * 32 + sec * 8;
            CP_ASYNC16(d,                 Ah + ga);
            CP_ASYNC16(d + MAT_BYTES,     Al + ga);
            CP_ASYNC16(d + 2 * MAT_BYTES, Bh + gb);
            CP_ASYNC16(d + 3 * MAT_BYTES, Bl + gb);
        }
    };

    load_chunk(0, 0);
    CP_COMMIT();

#pragma unroll 1
    for (int ch = 0; ch < 32; ch++) {
        if (ch + 1 < 32) { load_chunk((ch + 1) & 1, ch + 1); CP_COMMIT(); CP_WAIT1(); }
        else             { CP_WAIT0(); }
        __syncthreads();

        const char* stg = smem + (ch & 1) * STAGE_B4;
        const char* aB  = stg + (wm * 64) * 80;
        const char* bB  = stg + 2 * MAT_BYTES + (wn * 32) * 80;

#pragma unroll
        for (int ks = 0; ks < 2; ks++) {
            const int kb = (ks * 16 + kq) * 2;
            uint32_t bh[4][2], bl[4][2];
#pragma unroll
            for (int fn = 0; fn < 4; fn++) {
                const char* p = bB + (fn * 8 + r4) * 80 + kb;
                bh[fn][0] = *(const uint32_t*)p;
                bh[fn][1] = *(const uint32_t*)(p + 16);
                bl[fn][0] = *(const uint32_t*)(p + MAT_BYTES);
                bl[fn][1] = *(const uint32_t*)(p + MAT_BYTES + 16);
            }
#pragma unroll
            for (int fm = 0; fm < 4; fm++) {
                const char* p = aB + (fm * 16 + r4) * 80 + kb;
                uint32_t ah0 = *(const uint32_t*)p;
                uint32_t ah1 = *(const uint32_t*)(p + 8 * 80);
                uint32_t ah2 = *(const uint32_t*)(p + 16);
                uint32_t ah3 = *(const uint32_t*)(p + 8 * 80 + 16);
                uint32_t al0 = *(const uint32_t*)(p + MAT_BYTES);
                uint32_t al1 = *(const uint32_t*)(p + MAT_BYTES + 8 * 80);
                uint32_t al2 = *(const uint32_t*)(p + MAT_BYTES + 16);
                uint32_t al3 = *(const uint32_t*)(p + MAT_BYTES + 8 * 80 + 16);
#pragma unroll
                for (int fn = 0; fn < 4; fn++) {
                    mma16816(acc[fm][fn], ah0, ah1, ah2, ah3, bh[fn][0], bh[fn][1]);
                    mma16816(acc[fm][fn], ah0, ah1, ah2, ah3, bl[fn][0], bl[fn][1]);
                    mma16816(acc[fm][fn], al0, al1, al2, al3, bh[fn][0], bh[fn][1]);
                }
            }
        }
        __syncthreads();
    }

#pragma unroll
    for (int fm = 0; fm < 4; fm++) {
        const int row = mb * 128 + wm * 64 + fm * 16 + r4;
#pragma unroll
        for (int fn = 0; fn < 4; fn++) {
            const int col = nb * 128 + wn * 32 + fn * 8 + kq;
            float b0 = bias[col], b1 = bias[col + 1];
            *(float2*)&Cf[(size_t)row * DIM + col] =
                make_float2(acc[fm][fn][0] + b0, acc[fm][fn][1] + b1);
            *(float2*)&Cf[(size_t)(row + 8) * DIM + col] =
                make_float2(acc[fm][fn][2] + b0, acc[fm][fn][3] + b1);
        }
    }
}

// ---------------------------------------------------------------------------
// Flash attention (round-9 verbatim): bf16 3-term S and PV, Q frags resident,
// K split (144B stride) + V split transposed (272B stride), double-buffered.
// ---------------------------------------------------------------------------
#define KSTRIDE_B 144
#define VSTRIDE_B 272
#define KBYTES   (128 * KSTRIDE_B)            // 18432
#define VBYTES   (64 * VSTRIDE_B)             // 17408
#define STAGE_A  (2 * KBYTES + 2 * VBYTES)    // 71680
#define ATTN_SMEM (2 * STAGE_A)               // 143360

__global__ __launch_bounds__(256, 1) void attn_kernel()
{
    extern __shared__ char smem[];
    const uint32_t sb = smem_u32(smem);
    const int tid  = threadIdx.x;
    const int wid  = tid >> 5;
    const int lane = tid & 31;
    const int r4   = lane >> 2;
    const int kq   = (lane & 3) * 2;
    const int qb   = (gridDim.x - 1) - blockIdx.x;
    const int h    = blockIdx.y;
    const int hc   = h * HD;

    const int R0 = qb * 128 + wid * 16 + r4;
    const int R1 = R0 + 8;

    uint32_t qh[4][4], ql[4][4];
#pragma unroll
    for (int ks = 0; ks < 4; ks++) {
        const size_t k0 = (size_t)hc + ks * 16 + kq;
        qh[ks][0] = *(const uint32_t*)&g_Qh[(size_t)R0 * DIM + k0];
        qh[ks][1] = *(const uint32_t*)&g_Qh[(size_t)R1 * DIM + k0];
        qh[ks][2] = *(const uint32_t*)&g_Qh[(size_t)R0 * DIM + k0 + 8];
        qh[ks][3] = *(const uint32_t*)&g_Qh[(size_t)R1 * DIM + k0 + 8];
        ql[ks][0] = *(const uint32_t*)&g_Ql[(size_t)R0 * DIM + k0];
        ql[ks][1] = *(const uint32_t*)&g_Ql[(size_t)R1 * DIM + k0];
        ql[ks][2] = *(const uint32_t*)&g_Ql[(size_t)R0 * DIM + k0 + 8];
        ql[ks][3] = *(const uint32_t*)&g_Ql[(size_t)R1 * DIM + k0 + 8];
    }

    float o[8][4];
#pragma unroll
    for (int i = 0; i < 8; i++)
#pragma unroll
        for (int j = 0; j < 4; j++) o[i][j] = 0.0f;
    float m0 = -1e30f, m1 = -1e30f, l0 = 0.0f, l1 = 0.0f;

    auto load_stage = [&](int stg, int kb) {
        const uint32_t st = sb + stg * STAGE_A;
#pragma unroll
        for (int it = 0; it < 4; it++) {
            int i = tid + it * 256;
            int r = i >> 3, sec = i & 7;
            uint32_t d = st + r * KSTRIDE_B + sec * 16;
            size_t g = (size_t)(kb * 128 + r) * DIM + hc + sec * 8;
            CP_ASYNC16(d, g_Kh + g);
            CP_ASYNC16(d + KBYTES, g_Kl + g);
        }
        const uint32_t vst = st + 2 * KBYTES;
#pragma unroll
        for (int it = 0; it < 4; it++) {
            int i = tid + it * 256;
            int dd = i >> 4, sec = i & 15;
            uint32_t d = vst + dd * VSTRIDE_B + sec * 16;
            size_t g = (size_t)(hc + dd) * SEQ + kb * 128 + sec * 8;
            CP_ASYNC16(d, g_Vth + g);
            CP_ASYNC16(d + VBYTES, g_Vtl + g);
        }
    };

    load_stage(0, 0);
    CP_COMMIT();

#pragma unroll 1
    for (int kb = 0; kb <= qb; kb++) {
        if (kb < qb) { load_stage((kb + 1) & 1, kb + 1); CP_COMMIT(); CP_WAIT1(); }
        else         { CP_WAIT0(); }
        __syncthreads();

        const char* kbase = smem + (kb & 1) * STAGE_A;
        const char* vbase = kbase + 2 * KBYTES;

        float s[16][4];
#pragma unroll
        for (int nf = 0; nf < 16; nf++) {
#pragma unroll
            for (int q = 0; q < 4; q++) s[nf][q] = 0.0f;
#pragma unroll
            for (int ks = 0; ks < 4; ks++) {
                const char* p = kbase + (nf * 8 + r4) * KSTRIDE_B + (ks * 16 + kq) * 2;
                uint32_t bh0 = *(const uint32_t*)p;
                uint32_t bh1 = *(const uint32_t*)(p + 16);
                uint32_t bl0 = *(const uint32_t*)(p + KBYTES);
                uint32_t bl1 = *(const uint32_t*)(p + KBYTES + 16);
                mma16816(s[nf], qh[ks][0], qh[ks][1], qh[ks][2], qh[ks][3], bh0, bh1);
                mma16816(s[nf], qh[ks][0], qh[ks][1], qh[ks][2], qh[ks][3], bl0, bl1);
                mma16816(s[nf], ql[ks][0], ql[ks][1], ql[ks][2], ql[ks][3], bh0, bh1);
            }
        }

        if (kb == qb) {
#pragma unroll
            for (int nf = 0; nf < 16; nf++) {
                int C0 = kb * 128 + nf * 8 + kq;
                if (C0 > R0)     s[nf][0] = -1e30f;
                if (C0 + 1 > R0) s[nf][1] = -1e30f;
                if (C0 > R1)     s[nf][2] = -1e30f;
                if (C0 + 1 > R1) s[nf][3] = -1e30f;
            }
        }

        {
            float mx0 = m0, mx1 = m1;
#pragma unroll
            for (int nf = 0; nf < 16; nf++) {
                mx0 = fmaxf(mx0, fmaxf(s[nf][0], s[nf][1]));
                mx1 = fmaxf(mx1, fmaxf(s[nf][2], s[nf][3]));
            }
            mx0 = fmaxf(mx0, __shfl_xor_sync(0xffffffffu, mx0, 1));
            mx0 = fmaxf(mx0, __shfl_xor_sync(0xffffffffu, mx0, 2));
            mx1 = fmaxf(mx1, __shfl_xor_sync(0xffffffffu, mx1, 1));
            mx1 = fmaxf(mx1, __shfl_xor_sync(0xffffffffu, mx1, 2));
            float fac0 = __expf(m0 - mx0);
            float fac1 = __expf(m1 - mx1);
            m0 = mx0; m1 = mx1;
            float sum0 = 0.f, sum1 = 0.f;
#pragma unroll
            for (int nf = 0; nf < 16; nf++) {
                s[nf][0] = __expf(s[nf][0] - mx0);
                s[nf][1] = __expf(s[nf][1] - mx0);
                s[nf][2] = __expf(s[nf][2] - mx1);
                s[nf][3] = __expf(s[nf][3] - mx1);
                sum0 += s[nf][0] + s[nf][1];
                sum1 += s[nf][2] + s[nf][3];
            }
            sum0 += __shfl_xor_sync(0xffffffffu, sum0, 1);
            sum0 += __shfl_xor_sync(0xffffffffu, sum0, 2);
            sum1 += __shfl_xor_sync(0xffffffffu, sum1, 1);
            sum1 += __shfl_xor_sync(0xffffffffu, sum1, 2);
            l0 = l0 * fac0 + sum0;
            l1 = l1 * fac1 + sum1;
#pragma unroll
            for (int i = 0; i < 8; i++) {
                o[i][0] *= fac0; o[i][1] *= fac0;
                o[i][2] *= fac1; o[i][3] *= fac1;
            }
        }

#pragma unroll
        for (int kk = 0; kk < 8; kk++) {
            uint32_t ph[4], pl[4];
            split2(s[2 * kk][0],     s[2 * kk][1],     ph[0], pl[0]);
            split2(s[2 * kk][2],     s[2 * kk][3],     ph[1], pl[1]);
            split2(s[2 * kk + 1][0], s[2 * kk + 1][1], ph[2], pl[2]);
            split2(s[2 * kk + 1][2], s[2 * kk + 1][3], ph[3], pl[3]);
#pragma unroll
            for (int onf = 0; onf < 8; onf++) {
                const char* p = vbase + (onf * 8 + r4) * VSTRIDE_B + (kk * 16 + kq) * 2;
                uint32_t bh0 = *(const uint32_t*)p;
                uint32_t bh1 = *(const uint32_t*)(p + 16);
                uint32_t bl0 = *(const uint32_t*)(p + VBYTES);
                uint32_t bl1 = *(const uint32_t*)(p + VBYTES + 16);
                mma16816(o[onf], ph[0], ph[1], ph[2], ph[3], bh0, bh1);
                mma16816(o[onf], ph[0], ph[1], ph[2], ph[3], bl0, bl1);
                mma16816(o[onf], pl[0], pl[1], pl[2], pl[3], bh0, bh1);
            }
        }
        __syncthreads();
    }

    const float i0 = 1.0f / l0;
    const float i1 = 1.0f / l1;
#pragma unroll
    for (int onf = 0; onf < 8; onf++) {
        uint32_t hi, lo;
        const size_t c0 = (size_t)hc + onf * 8 + kq;
        split2(o[onf][0] * i0, o[onf][1] * i0, hi, lo);
        *(uint32_t*)&g_ch[(size_t)R0 * DIM + c0] = hi;
        *(uint32_t*)&g_cl[(size_t)R0 * DIM + c0] = lo;
        split2(o[onf][2] * i1, o[onf][3] * i1, hi, lo);
        *(uint32_t*)&g_ch[(size_t)R1 * DIM + c0] = hi;
        *(uint32_t*)&g_cl[(size_t)R1 * DIM + c0] = lo;
    }
}

extern "C" void kernel_launch(void* const* d_in, const int* in_sizes, int n_in,
                              void* d_out, int out_size)
{
    (void)in_sizes; (void)n_in; (void)out_size;
    const float* x  = (const float*)d_in[0];
    const float* Wq = (const float*)d_in[1];
    const float* Wk = (const float*)d_in[2];
    const float* Wv = (const float*)d_in[3];
    const float* Wo = (const float*)d_in[4];
    const float* bo = (const float*)d_in[5];
    float* out = (float*)d_out;

    static bool attr_set = false;
    if (!attr_set) {
        cudaFuncSetAttribute(attn_kernel,
                             cudaFuncAttributeMaxDynamicSharedMemorySize, ATTN_SMEM);
        cudaFuncSetAttribute(mm_qkv_i8_kernel,
                             cudaFuncAttributeMaxDynamicSharedMemorySize, MM_SMEM_I);
        cudaFuncSetAttribute(mm_out_kernel,
                             cudaFuncAttributeMaxDynamicSharedMemorySize, MM_SMEM_B);
        attr_set = true;
    }

    // 1) conversions
    convert_i8_kernel<<<SEQ * 128 / 256, 256>>>(x,  0, SEQ, 127.0f / SX_MAX);
    convert_i8_kernel<<<DIM * 128 / 256, 256>>>(Wq, 1, DIM, 127.0f / SW_MAX);
    convert_i8_kernel<<<DIM * 128 / 256, 256>>>(Wk, 2, DIM, 127.0f / SW_MAX);
    convert_i8_kernel<<<DIM * 128 / 256, 256>>>(Wv, 3, DIM, 127.0f / SW_MAX);
    convert_bf16_kernel<<<DIM * 128 / 256, 256>>>(Wo);

    // 2) Q/K/V projections on int8 IMMA (split-bf16 epilogues)
    {
        dim3 grid(DIM / 128, SEQ / 128, 3);
        mm_qkv_i8_kernel<<<grid, 256, MM_SMEM_I>>>();
    }
    // 3) causal flash attention (bf16 3-term, round-9)
    {
        dim3 grid(SEQ / 128, NH);
        attn_kernel<<<grid, 256, ATTN_SMEM>>>();
    }
    // 4) output projection + bias (bf16 3-term, round-9)
    {
        dim3 grid(DIM / 128, SEQ / 128, 1);
        mm_out_kernel<<<grid, 256, MM_SMEM_B>>>(bo, out);
    }
}

// round 14
// speedup vs baseline: 1.3459x; 1.3459x over previous
#include <cuda_runtime.h>
#include <cuda_bf16.h>
#include <cstdint>
#include <math.h>

#define SEQ 4096
#define DIM 1024
#define NH  16
#define HD  64

// ---------------------------------------------------------------------------
// Scratch (allocation-free rule: __device__ globals). All bf16-split pairs.
// ---------------------------------------------------------------------------
__device__ __align__(16) __nv_bfloat16 g_xh[SEQ * DIM],  g_xl[SEQ * DIM];
__device__ __align__(16) __nv_bfloat16 g_ch[SEQ * DIM],  g_cl[SEQ * DIM];
__device__ __align__(16) __nv_bfloat16 g_Qh[SEQ * DIM],  g_Ql[SEQ * DIM];   // pre-scaled 0.125
__device__ __align__(16) __nv_bfloat16 g_Kh[SEQ * DIM],  g_Kl[SEQ * DIM];
__device__ __align__(16) __nv_bfloat16 g_Vth[DIM * SEQ], g_Vtl[DIM * SEQ];  // transposed [dim][seq]
__device__ __align__(16) __nv_bfloat16 g_Wqh[DIM * DIM], g_Wql[DIM * DIM];
__device__ __align__(16) __nv_bfloat16 g_Wkh[DIM * DIM], g_Wkl[DIM * DIM];
__device__ __align__(16) __nv_bfloat16 g_Wvh[DIM * DIM], g_Wvl[DIM * DIM];
__device__ __align__(16) __nv_bfloat16 g_Woh[DIM * DIM], g_Wol[DIM * DIM];

// ---------------------------------------------------------------------------
// PTX helpers (baseline PTX only — compute_103-safe)
// ---------------------------------------------------------------------------
__device__ __forceinline__ uint32_t smem_u32(const void* p) {
    uint32_t a;
    asm("{ .reg .u64 t; cvta.to.shared.u64 t, %1; cvt.u32.u64 %0, t; }"
        : "=r"(a) : "l"(p));
    return a;
}
#define CP_ASYNC16(dst, src) \
    asm volatile("cp.async.ca.shared.global [%0], [%1], 16;" \
                 :: "r"(dst), "l"(src) : "memory")
#define CP_COMMIT()  asm volatile("cp.async.commit_group;" ::: "memory")
#define CP_WAIT1()   asm volatile("cp.async.wait_group 1;" ::: "memory")
#define CP_WAIT0()   asm volatile("cp.async.wait_group 0;" ::: "memory")

__device__ __forceinline__ void mma16816(float* c,
                                         uint32_t a0, uint32_t a1, uint32_t a2, uint32_t a3,
                                         uint32_t b0, uint32_t b1) {
    asm volatile(
        "mma.sync.aligned.m16n8k16.row.col.f32.bf16.bf16.f32 "
        "{%0,%1,%2,%3}, {%4,%5,%6,%7}, {%8,%9}, {%0,%1,%2,%3};"
        : "+f"(c[0]), "+f"(c[1]), "+f"(c[2]), "+f"(c[3])
        : "r"(a0), "r"(a1), "r"(a2), "r"(a3), "r"(b0), "r"(b1));
}

__device__ __forceinline__ void split2(float v0, float v1, uint32_t& hi, uint32_t& lo) {
    __nv_bfloat16 h0 = __float2bfloat16(v0), h1 = __float2bfloat16(v1);
    __nv_bfloat16 l0 = __float2bfloat16(v0 - __bfloat162float(h0));
    __nv_bfloat16 l1 = __float2bfloat16(v1 - __bfloat162float(h1));
    hi = ((uint32_t)__bfloat16_as_ushort(h1) << 16) | __bfloat16_as_ushort(h0);
    lo = ((uint32_t)__bfloat16_as_ushort(l1) << 16) | __bfloat16_as_ushort(l0);
}

// ---------------------------------------------------------------------------
// Fused converter: x, Wq, Wk, Wv, Wo -> bf16 split in ONE launch.
// Row space: [0,4096)=x, then 4x1024 for Wq,Wk,Wv,Wo.
// ---------------------------------------------------------------------------
__global__ __launch_bounds__(256) void convert_all_kernel(const float* __restrict__ x,
                                                          const float* __restrict__ Wq,
                                                          const float* __restrict__ Wk,
                                                          const float* __restrict__ Wv,
                                                          const float* __restrict__ Wo)
{
    int id = blockIdx.x * 256 + threadIdx.x;
    int r = id >> 7;                    // 0..8191
    int c = (id & 127) << 3;

    const float* src;
    __nv_bfloat16 *dh, *dl;
    int rr;
    if (r < SEQ) {
        src = x;  dh = g_xh;  dl = g_xl;  rr = r;
    } else {
        int t = (r - SEQ) >> 10;
        rr = (r - SEQ) & 1023;
        switch (t) {
            case 0: src = Wq; dh = g_Wqh; dl = g_Wql; break;
            case 1: src = Wk; dh = g_Wkh; dl = g_Wkl; break;
            case 2: src = Wv; dh = g_Wvh; dl = g_Wvl; break;
            default: src = Wo; dh = g_Woh; dl = g_Wol; break;
        }
    }
    size_t off = (size_t)rr * DIM + c;

    float4 v0 = *(const float4*)&src[off];
    float4 v1 = *(const float4*)&src[off + 4];
    float v[8] = {v0.x, v0.y, v0.z, v0.w, v1.x, v1.y, v1.z, v1.w};

    union { uint4 u; __nv_bfloat16 b[8]; } H, L;
#pragma unroll
    for (int i = 0; i < 8; i++) {
        __nv_bfloat16 h = __float2bfloat16(v[i]);
        H.b[i] = h;
        L.b[i] = __float2bfloat16(v[i] - __bfloat162float(h));
    }
    *(uint4*)&dh[off] = H.u;
    *(uint4*)&dl[off] = L.u;
}

// ---------------------------------------------------------------------------
// bf16 3-term GEMM core (round-9 verbatim): C = A @ B^T.
// CTA 128x128, 8 warps (2x4), k-chunk 32, cp.async double-buffered.
// Epilogue modes: 0 fp32+bias, 1 split-bf16 row-major*scale, 2 split-bf16 transposed.
// ---------------------------------------------------------------------------
#define MAT_BYTES   (128 * 40 * 2)            // 10240
#define STAGE_BYTES (4 * MAT_BYTES)           // 40960
#define MM_SMEM     (2 * STAGE_BYTES)         // 81920

__device__ __forceinline__ void mm_load_chunk(uint32_t sb, int stage, int ch,
                                              const __nv_bfloat16* Ah,
                                              const __nv_bfloat16* Al,
                                              const __nv_bfloat16* Bh,
                                              const __nv_bfloat16* Bl,
                                              int mb, int nb, int tid)
{
    const uint32_t st = sb + stage * STAGE_BYTES;
#pragma unroll
    for (int it = 0; it < 2; it++) {
        int i = tid + it * 256;
        int r = i >> 2;
        int sec = i & 3;
        uint32_t d = st + r * 80 + sec * 16;
        size_t ga = (size_t)(mb * 128 + r) * DIM + ch * 32 + sec * 8;
        size_t gb = (size_t)(nb * 128 + r) * DIM + ch * 32 + sec * 8;
        CP_ASYNC16(d,                 Ah + ga);
        CP_ASYNC16(d + MAT_BYTES,     Al + ga);
        CP_ASYNC16(d + 2 * MAT_BYTES, Bh + gb);
        CP_ASYNC16(d + 3 * MAT_BYTES, Bl + gb);
    }
}

__device__ __forceinline__ void mm_tile(const __nv_bfloat16* __restrict__ Ah,
                                        const __nv_bfloat16* __restrict__ Al,
                                        const __nv_bfloat16* __restrict__ Bh,
                                        const __nv_bfloat16* __restrict__ Bl,
                                        float* __restrict__ Cf,
                                        const float* __restrict__ bias,
                                        __nv_bfloat16* __restrict__ Dh,
                                        __nv_bfloat16* __restrict__ Dl,
                                        int mode, float scale)
{
    extern __shared__ char smem[];
    const uint32_t sb = smem_u32(smem);
    const int tid  = threadIdx.x;
    const int wid  = tid >> 5;
    const int lane = tid & 31;
    const int wm   = wid & 1;
    const int wn   = wid >> 1;
    const int mb   = blockIdx.y;
    const int nb   = blockIdx.x;

    const int r4 = lane >> 2;
    const int kq = (lane & 3) * 2;

    float acc[4][4][4];
#pragma unroll
    for (int fm = 0; fm < 4; fm++)
#pragma unroll
        for (int fn = 0; fn < 4; fn++)
#pragma unroll
            for (int q = 0; q < 4; q++) acc[fm][fn][q] = 0.0f;

    mm_load_chunk(sb, 0, 0, Ah, Al, Bh, Bl, mb, nb, tid);
    CP_COMMIT();

#pragma unroll 1
    for (int ch = 0; ch < 32; ch++) {
        if (ch + 1 < 32) {
            mm_load_chunk(sb, (ch + 1) & 1, ch + 1, Ah, Al, Bh, Bl, mb, nb, tid);
            CP_COMMIT();
            CP_WAIT1();
        } else {
            CP_WAIT0();
        }
        __syncthreads();

        const char* stg = smem + (ch & 1) * STAGE_BYTES;
        const char* aB  = stg + (wm * 64) * 80;
        const char* bB  = stg + 2 * MAT_BYTES + (wn * 32) * 80;

#pragma unroll
        for (int ks = 0; ks < 2; ks++) {
            const int kb = (ks * 16 + kq) * 2;
            uint32_t bh[4][2], bl[4][2];
#pragma unroll
            for (int fn = 0; fn < 4; fn++) {
                const char* p = bB + (fn * 8 + r4) * 80 + kb;
                bh[fn][0] = *(const uint32_t*)p;
                bh[fn][1] = *(const uint32_t*)(p + 16);
                bl[fn][0] = *(const uint32_t*)(p + MAT_BYTES);
                bl[fn][1] = *(const uint32_t*)(p + MAT_BYTES + 16);
            }
#pragma unroll
            for (int fm = 0; fm < 4; fm++) {
                const char* p = aB + (fm * 16 + r4) * 80 + kb;
                uint32_t ah0 = *(const uint32_t*)p;
                uint32_t ah1 = *(const uint32_t*)(p + 8 * 80);
                uint32_t ah2 = *(const uint32_t*)(p + 16);
                uint32_t ah3 = *(const uint32_t*)(p + 8 * 80 + 16);
                uint32_t al0 = *(const uint32_t*)(p + MAT_BYTES);
                uint32_t al1 = *(const uint32_t*)(p + MAT_BYTES + 8 * 80);
                uint32_t al2 = *(const uint32_t*)(p + MAT_BYTES + 16);
                uint32_t al3 = *(const uint32_t*)(p + MAT_BYTES + 8 * 80 + 16);
#pragma unroll
                for (int fn = 0; fn < 4; fn++) {
                    mma16816(acc[fm][fn], ah0, ah1, ah2, ah3, bh[fn][0], bh[fn][1]);
                    mma16816(acc[fm][fn], ah0, ah1, ah2, ah3, bl[fn][0], bl[fn][1]);
                    mma16816(acc[fm][fn], al0, al1, al2, al3, bh[fn][0], bh[fn][1]);
                }
            }
        }
        __syncthreads();
    }

    // epilogue
#pragma unroll
    for (int fm = 0; fm < 4; fm++) {
        const int row = mb * 128 + wm * 64 + fm * 16 + r4;
#pragma unroll
        for (int fn = 0; fn < 4; fn++) {
            const int col = nb * 128 + wn * 32 + fn * 8 + kq;
            float v0 = acc[fm][fn][0], v1 = acc[fm][fn][1];
            float v2 = acc[fm][fn][2], v3 = acc[fm][fn][3];
            if (mode == 0) {
                float b0 = bias ? bias[col] : 0.f, b1 = bias ? bias[col + 1] : 0.f;
                *(float2*)&Cf[(size_t)row * DIM + col] = make_float2(v0 + b0, v1 + b1);
                *(float2*)&Cf[(size_t)(row + 8) * DIM + col] = make_float2(v2 + b0, v3 + b1);
            } else if (mode == 1) {
                uint32_t hi, lo;
                split2(v0 * scale, v1 * scale, hi, lo);
                *(uint32_t*)&Dh[(size_t)row * DIM + col] = hi;
                *(uint32_t*)&Dl[(size_t)row * DIM + col] = lo;
                split2(v2 * scale, v3 * scale, hi, lo);
                *(uint32_t*)&Dh[(size_t)(row + 8) * DIM + col] = hi;
                *(uint32_t*)&Dl[(size_t)(row + 8) * DIM + col] = lo;
            } else {
                __nv_bfloat16 h, l;
                h = __float2bfloat16(v0); l = __float2bfloat16(v0 - __bfloat162float(h));
                Dh[(size_t)col * SEQ + row] = h;       Dl[(size_t)col * SEQ + row] = l;
                h = __float2bfloat16(v1); l = __float2bfloat16(v1 - __bfloat162float(h));
                Dh[(size_t)(col + 1) * SEQ + row] = h; Dl[(size_t)(col + 1) * SEQ + row] = l;
                h = __float2bfloat16(v2); l = __float2bfloat16(v2 - __bfloat162float(h));
                Dh[(size_t)col * SEQ + row + 8] = h;   Dl[(size_t)col * SEQ + row + 8] = l;
                h = __float2bfloat16(v3); l = __float2bfloat16(v3 - __bfloat162float(h));
                Dh[(size_t)(col + 1) * SEQ + row + 8] = h; Dl[(size_t)(col + 1) * SEQ + row + 8] = l;
            }
        }
    }
}

__global__ __launch_bounds__(256) void mm_qkv_kernel()
{
    if (blockIdx.z == 0)
        mm_tile(g_xh, g_xl, g_Wqh, g_Wql, nullptr, nullptr, g_Qh, g_Ql, 1, 0.125f);
    else if (blockIdx.z == 1)
        mm_tile(g_xh, g_xl, g_Wkh, g_Wkl, nullptr, nullptr, g_Kh, g_Kl, 1, 1.0f);
    else
        mm_tile(g_xh, g_xl, g_Wvh, g_Wvl, nullptr, nullptr, g_Vth, g_Vtl, 2, 1.0f);
}

__global__ __launch_bounds__(256) void mm_out_kernel(const float* __restrict__ bo,
                                                     float* __restrict__ out)
{
    mm_tile(g_ch, g_cl, g_Woh, g_Wol, out, bo, nullptr, nullptr, 0, 1.0f);
}

// ---------------------------------------------------------------------------
// Flash attention (round-9 + diagonal-block work skips).
// S = QK^T bf16 3-term; PV bf16 3-term. Q frags register-resident.
// Diag skips: S frags fully above the diagonal are not computed (set -1e30);
// PV iterations whose P fragments are all zero are skipped.
// ---------------------------------------------------------------------------
#define KSTRIDE_B 144
#define VSTRIDE_B 272
#define KBYTES   (128 * KSTRIDE_B)            // 18432
#define VBYTES   (64 * VSTRIDE_B)             // 17408
#define STAGE_A  (2 * KBYTES + 2 * VBYTES)    // 71680
#define ATTN_SMEM (2 * STAGE_A)               // 143360

__global__ __launch_bounds__(256, 1) void attn_kernel()
{
    extern __shared__ char smem[];
    const uint32_t sb = smem_u32(smem);
    const int tid  = threadIdx.x;
    const int wid  = tid >> 5;
    const int lane = tid & 31;
    const int r4   = lane >> 2;
    const int kq   = (lane & 3) * 2;
    const int qb   = (gridDim.x - 1) - blockIdx.x;
    const int h    = blockIdx.y;
    const int hc   = h * HD;

    const int R0 = qb * 128 + wid * 16 + r4;
    const int R1 = R0 + 8;
    const int nf_lim = 2 * wid + 2;      // diag: frags nf >= nf_lim fully masked
    const int kk_lim = wid + 1;          // diag: PV iters kk >= kk_lim have P == 0

    uint32_t qh[4][4], ql[4][4];
#pragma unroll
    for (int ks = 0; ks < 4; ks++) {
        const size_t k0 = (size_t)hc + ks * 16 + kq;
        qh[ks][0] = *(const uint32_t*)&g_Qh[(size_t)R0 * DIM + k0];
        qh[ks][1] = *(const uint32_t*)&g_Qh[(size_t)R1 * DIM + k0];
        qh[ks][2] = *(const uint32_t*)&g_Qh[(size_t)R0 * DIM + k0 + 8];
        qh[ks][3] = *(const uint32_t*)&g_Qh[(size_t)R1 * DIM + k0 + 8];
        ql[ks][0] = *(const uint32_t*)&g_Ql[(size_t)R0 * DIM + k0];
        ql[ks][1] = *(const uint32_t*)&g_Ql[(size_t)R1 * DIM + k0];
        ql[ks][2] = *(const uint32_t*)&g_Ql[(size_t)R0 * DIM + k0 + 8];
        ql[ks][3] = *(const uint32_t*)&g_Ql[(size_t)R1 * DIM + k0 + 8];
    }

    float o[8][4];
#pragma unroll
    for (int i = 0; i < 8; i++)
#pragma unroll
        for (int j = 0; j < 4; j++) o[i][j] = 0.0f;
    float m0 = -1e30f, m1 = -1e30f, l0 = 0.0f, l1 = 0.0f;

    auto load_stage = [&](int stg, int kb) {
        const uint32_t st = sb + stg * STAGE_A;
#pragma unroll
        for (int it = 0; it < 4; it++) {
            int i = tid + it * 256;
            int r = i >> 3, sec = i & 7;
            uint32_t d = st + r * KSTRIDE_B + sec * 16;
            size_t g = (size_t)(kb * 128 + r) * DIM + hc + sec * 8;
            CP_ASYNC16(d, g_Kh + g);
            CP_ASYNC16(d + KBYTES, g_Kl + g);
        }
        const uint32_t vst = st + 2 * KBYTES;
#pragma unroll
        for (int it = 0; it < 4; it++) {
            int i = tid + it * 256;
            int dd = i >> 4, sec = i & 15;
            uint32_t d = vst + dd * VSTRIDE_B + sec * 16;
            size_t g = (size_t)(hc + dd) * SEQ + kb * 128 + sec * 8;
            CP_ASYNC16(d, g_Vth + g);
            CP_ASYNC16(d + VBYTES, g_Vtl + g);
        }
    };

    load_stage(0, 0);
    CP_COMMIT();

#pragma unroll 1
    for (int kb = 0; kb <= qb; kb++) {
        if (kb < qb) { load_stage((kb + 1) & 1, kb + 1); CP_COMMIT(); CP_WAIT1(); }
        else         { CP_WAIT0(); }
        __syncthreads();

        const char* kbase = smem + (kb & 1) * STAGE_A;
        const char* vbase = kbase + 2 * KBYTES;
        const bool diag = (kb == qb);

        // S = Q @ K^T (bf16 3-term), skipping fully-masked diag frags
        float s[16][4];
#pragma unroll
        for (int nf = 0; nf < 16; nf++) {
            if (diag && nf >= nf_lim) {
                s[nf][0] = -1e30f; s[nf][1] = -1e30f;
                s[nf][2] = -1e30f; s[nf][3] = -1e30f;
                continue;
            }
#pragma unroll
            for (int q = 0; q < 4; q++) s[nf][q] = 0.0f;
#pragma unroll
            for (int ks = 0; ks < 4; ks++) {
                const char* p = kbase + (nf * 8 + r4) * KSTRIDE_B + (ks * 16 + kq) * 2;
                uint32_t bh0 = *(const uint32_t*)p;
                uint32_t bh1 = *(const uint32_t*)(p + 16);
                uint32_t bl0 = *(const uint32_t*)(p + KBYTES);
                uint32_t bl1 = *(const uint32_t*)(p + KBYTES + 16);
                mma16816(s[nf], qh[ks][0], qh[ks][1], qh[ks][2], qh[ks][3], bh0, bh1);
                mma16816(s[nf], qh[ks][0], qh[ks][1], qh[ks][2], qh[ks][3], bl0, bl1);
                mma16816(s[nf], ql[ks][0], ql[ks][1], ql[ks][2], ql[ks][3], bh0, bh1);
            }
        }

        if (diag) {
#pragma unroll
            for (int nf = 0; nf < 16; nf++) {
                int C0 = kb * 128 + nf * 8 + kq;
                if (C0 > R0)     s[nf][0] = -1e30f;
                if (C0 + 1 > R0) s[nf][1] = -1e30f;
                if (C0 > R1)     s[nf][2] = -1e30f;
                if (C0 + 1 > R1) s[nf][3] = -1e30f;
            }
        }

        // online softmax
        {
            float mx0 = m0, mx1 = m1;
#pragma unroll
            for (int nf = 0; nf < 16; nf++) {
                mx0 = fmaxf(mx0, fmaxf(s[nf][0], s[nf][1]));
                mx1 = fmaxf(mx1, fmaxf(s[nf][2], s[nf][3]));
            }
            mx0 = fmaxf(mx0, __shfl_xor_sync(0xffffffffu, mx0, 1));
            mx0 = fmaxf(mx0, __shfl_xor_sync(0xffffffffu, mx0, 2));
            mx1 = fmaxf(mx1, __shfl_xor_sync(0xffffffffu, mx1, 1));
            mx1 = fmaxf(mx1, __shfl_xor_sync(0xffffffffu, mx1, 2));
            float fac0 = __expf(m0 - mx0);
            float fac1 = __expf(m1 - mx1);
            m0 = mx0; m1 = mx1;
            float sum0 = 0.f, sum1 = 0.f;
#pragma unroll
            for (int nf = 0; nf < 16; nf++) {
                s[nf][0] = __expf(s[nf][0] - mx0);
                s[nf][1] = __expf(s[nf][1] - mx0);
                s[nf][2] = __expf(s[nf][2] - mx1);
                s[nf][3] = __expf(s[nf][3] - mx1);
                sum0 += s[nf][0] + s[nf][1];
                sum1 += s[nf][2] + s[nf][3];
            }
            sum0 += __shfl_xor_sync(0xffffffffu, sum0, 1);
            sum0 += __shfl_xor_sync(0xffffffffu, sum0, 2);
            sum1 += __shfl_xor_sync(0xffffffffu, sum1, 1);
            sum1 += __shfl_xor_sync(0xffffffffu, sum1, 2);
            l0 = l0 * fac0 + sum0;
            l1 = l1 * fac1 + sum1;
#pragma unroll
            for (int i = 0; i < 8; i++) {
                o[i][0] *= fac0; o[i][1] *= fac0;
                o[i][2] *= fac1; o[i][3] *= fac1;
            }
        }

        // O += P @ V (bf16 3-term), skipping zero-P diag iterations
#pragma unroll
        for (int kk = 0; kk < 8; kk++) {
            if (diag && kk >= kk_lim) break;
            uint32_t ph[4], pl[4];
            split2(s[2 * kk][0],     s[2 * kk][1],     ph[0], pl[0]);
            split2(s[2 * kk][2],     s[2 * kk][3],     ph[1], pl[1]);
            split2(s[2 * kk + 1][0], s[2 * kk + 1][1], ph[2], pl[2]);
            split2(s[2 * kk + 1][2], s[2 * kk + 1][3], ph[3], pl[3]);
#pragma unroll
            for (int onf = 0; onf < 8; onf++) {
                const char* p = vbase + (onf * 8 + r4) * VSTRIDE_B + (kk * 16 + kq) * 2;
                uint32_t bh0 = *(const uint32_t*)p;
                uint32_t bh1 = *(const uint32_t*)(p + 16);
                uint32_t bl0 = *(const uint32_t*)(p + VBYTES);
                uint32_t bl1 = *(const uint32_t*)(p + VBYTES + 16);
                mma16816(o[onf], ph[0], ph[1], ph[2], ph[3], bh0, bh1);
                mma16816(o[onf], ph[0], ph[1], ph[2], ph[3], bl0, bl1);
                mma16816(o[onf], pl[0], pl[1], pl[2], pl[3], bh0, bh1);
            }
        }
        __syncthreads();
    }

    // epilogue: normalize, split to bf16, store ctx
    const float i0 = 1.0f / l0;
    const float i1 = 1.0f / l1;
#pragma unroll
    for (int onf = 0; onf < 8; onf++) {
        uint32_t hi, lo;
        const size_t c0 = (size_t)hc + onf * 8 + kq;
        split2(o[onf][0] * i0, o[onf][1] * i0, hi, lo);
        *(uint32_t*)&g_ch[(size_t)R0 * DIM + c0] = hi;
        *(uint32_t*)&g_cl[(size_t)R0 * DIM + c0] = lo;
        split2(o[onf][2] * i1, o[onf][3] * i1, hi, lo);
        *(uint32_t*)&g_ch[(size_t)R1 * DIM + c0] = hi;
        *(uint32_t*)&g_cl[(size_t)R1 * DIM + c0] = lo;
    }
}

extern "C" void kernel_launch(void* const* d_in, const int* in_sizes, int n_in,
                              void* d_out, int out_size)
{
    (void)in_sizes; (void)n_in; (void)out_size;
    const float* x  = (const float*)d_in[0];
    const float* Wq = (const float*)d_in[1];
    const float* Wk = (const float*)d_in[2];
    const float* Wv = (const float*)d_in[3];
    const float* Wo = (const float*)d_in[4];
    const float* bo = (const float*)d_in[5];
    float* out = (float*)d_out;

    static bool attr_set = false;
    if (!attr_set) {
        cudaFuncSetAttribute(attn_kernel,
                             cudaFuncAttributeMaxDynamicSharedMemorySize, ATTN_SMEM);
        cudaFuncSetAttribute(mm_qkv_kernel,
                             cudaFuncAttributeMaxDynamicSharedMemorySize, MM_SMEM);
        cudaFuncSetAttribute(mm_out_kernel,
                             cudaFuncAttributeMaxDynamicSharedMemorySize, MM_SMEM);
        attr_set = true;
    }

    // 1) single fused conversion pass (x + 4 weights -> bf16 split)
    convert_all_kernel<<<(SEQ + 4 * DIM) * 128 / 256, 256>>>(x, Wq, Wk, Wv, Wo);

    // 2) Q/K/V projections (split-bf16 epilogues; Q scaled, V transposed)
    {
        dim3 grid(DIM / 128, SEQ / 128, 3);
        mm_qkv_kernel<<<grid, 256, MM_SMEM>>>();
    }
    // 3) causal flash attention (bf16 3-term + diag skips)
    {
        dim3 grid(SEQ / 128, NH);
        attn_kernel<<<grid, 256, ATTN_SMEM>>>();
    }
    // 4) output projection + bias
    {
        dim3 grid(DIM / 128, SEQ / 128, 1);
        mm_out_kernel<<<grid, 256, MM_SMEM>>>(bo, out);
    }
}

// round 16
// speedup vs baseline: 1.7540x; 1.3032x over previous
#include <cuda_runtime.h>
#include <cuda_bf16.h>
#include <cstdint>
#include <math.h>

#define SEQ 4096
#define DIM 1024
#define NH  16
#define HD  64

// ---------------------------------------------------------------------------
// Scratch (allocation-free rule: __device__ globals). All bf16-split pairs.
// ---------------------------------------------------------------------------
__device__ __align__(16) __nv_bfloat16 g_xh[SEQ * DIM],  g_xl[SEQ * DIM];
__device__ __align__(16) __nv_bfloat16 g_ch[SEQ * DIM],  g_cl[SEQ * DIM];
__device__ __align__(16) __nv_bfloat16 g_Qh[SEQ * DIM],  g_Ql[SEQ * DIM];   // pre-scaled 0.125
__device__ __align__(16) __nv_bfloat16 g_Kh[SEQ * DIM],  g_Kl[SEQ * DIM];
__device__ __align__(16) __nv_bfloat16 g_Vth[DIM * SEQ], g_Vtl[DIM * SEQ];  // transposed [dim][seq]
__device__ __align__(16) __nv_bfloat16 g_Wqh[DIM * DIM], g_Wql[DIM * DIM];
__device__ __align__(16) __nv_bfloat16 g_Wkh[DIM * DIM], g_Wkl[DIM * DIM];
__device__ __align__(16) __nv_bfloat16 g_Wvh[DIM * DIM], g_Wvl[DIM * DIM];
__device__ __align__(16) __nv_bfloat16 g_Woh[DIM * DIM], g_Wol[DIM * DIM];

// ---------------------------------------------------------------------------
// PTX helpers (baseline PTX only — compute_103-safe)
// ---------------------------------------------------------------------------
__device__ __forceinline__ uint32_t smem_u32(const void* p) {
    uint32_t a;
    asm("{ .reg .u64 t; cvta.to.shared.u64 t, %1; cvt.u32.u64 %0, t; }"
        : "=r"(a) : "l"(p));
    return a;
}
#define CP_ASYNC16(dst, src) \
    asm volatile("cp.async.ca.shared.global [%0], [%1], 16;" \
                 :: "r"(dst), "l"(src) : "memory")
#define CP_COMMIT()  asm volatile("cp.async.commit_group;" ::: "memory")
#define CP_WAIT1()   asm volatile("cp.async.wait_group 1;" ::: "memory")
#define CP_WAIT0()   asm volatile("cp.async.wait_group 0;" ::: "memory")

__device__ __forceinline__ void mma16816(float* c,
                                         uint32_t a0, uint32_t a1, uint32_t a2, uint32_t a3,
                                         uint32_t b0, uint32_t b1) {
    asm volatile(
        "mma.sync.aligned.m16n8k16.row.col.f32.bf16.bf16.f32 "
        "{%0,%1,%2,%3}, {%4,%5,%6,%7}, {%8,%9}, {%0,%1,%2,%3};"
        : "+f"(c[0]), "+f"(c[1]), "+f"(c[2]), "+f"(c[3])
        : "r"(a0), "r"(a1), "r"(a2), "r"(a3), "r"(b0), "r"(b1));
}

__device__ __forceinline__ void split2(float v0, float v1, uint32_t& hi, uint32_t& lo) {
    __nv_bfloat16 h0 = __float2bfloat16(v0), h1 = __float2bfloat16(v1);
    __nv_bfloat16 l0 = __float2bfloat16(v0 - __bfloat162float(h0));
    __nv_bfloat16 l1 = __float2bfloat16(v1 - __bfloat162float(h1));
    hi = ((uint32_t)__bfloat16_as_ushort(h1) << 16) | __bfloat16_as_ushort(h0);
    lo = ((uint32_t)__bfloat16_as_ushort(l1) << 16) | __bfloat16_as_ushort(l0);
}

// ---------------------------------------------------------------------------
// Fused converter: x, Wq, Wk, Wv, Wo -> bf16 split in ONE launch.
// ---------------------------------------------------------------------------
__global__ __launch_bounds__(256) void convert_all_kernel(const float* __restrict__ x,
                                                          const float* __restrict__ Wq,
                                                          const float* __restrict__ Wk,
                                                          const float* __restrict__ Wv,
                                                          const float* __restrict__ Wo)
{
    int id = blockIdx.x * 256 + threadIdx.x;
    int r = id >> 7;                    // 0..8191
    int c = (id & 127) << 3;

    const float* src;
    __nv_bfloat16 *dh, *dl;
    int rr;
    if (r < SEQ) {
        src = x;  dh = g_xh;  dl = g_xl;  rr = r;
    } else {
        int t = (r - SEQ) >> 10;
        rr = (r - SEQ) & 1023;
        switch (t) {
            case 0: src = Wq; dh = g_Wqh; dl = g_Wql; break;
            case 1: src = Wk; dh = g_Wkh; dl = g_Wkl; break;
            case 2: src = Wv; dh = g_Wvh; dl = g_Wvl; break;
            default: src = Wo; dh = g_Woh; dl = g_Wol; break;
        }
    }
    size_t off = (size_t)rr * DIM + c;

    float4 v0 = *(const float4*)&src[off];
    float4 v1 = *(const float4*)&src[off + 4];
    float v[8] = {v0.x, v0.y, v0.z, v0.w, v1.x, v1.y, v1.z, v1.w};

    union { uint4 u; __nv_bfloat16 b[8]; } H, L;
#pragma unroll
    for (int i = 0; i < 8; i++) {
        __nv_bfloat16 h = __float2bfloat16(v[i]);
        H.b[i] = h;
        L.b[i] = __float2bfloat16(v[i] - __bfloat162float(h));
    }
    *(uint4*)&dh[off] = H.u;
    *(uint4*)&dl[off] = L.u;
}

// ---------------------------------------------------------------------------
// bf16 3-term GEMM core (round-9 verbatim): C = A @ B^T.
// CTA 128x128, 8 warps (2x4), k-chunk 32, cp.async double-buffered.
// Epilogue modes: 0 fp32+bias, 1 split-bf16 row-major*scale, 2 split-bf16 transposed.
// ---------------------------------------------------------------------------
#define MAT_BYTES   (128 * 40 * 2)            // 10240
#define STAGE_BYTES (4 * MAT_BYTES)           // 40960
#define MM_SMEM     (2 * STAGE_BYTES)         // 81920

__device__ __forceinline__ void mm_load_chunk(uint32_t sb, int stage, int ch,
                                              const __nv_bfloat16* Ah,
                                              const __nv_bfloat16* Al,
                                              const __nv_bfloat16* Bh,
                                              const __nv_bfloat16* Bl,
                                              int mb, int nb, int tid)
{
    const uint32_t st = sb + stage * STAGE_BYTES;
#pragma unroll
    for (int it = 0; it < 2; it++) {
        int i = tid + it * 256;
        int r = i >> 2;
        int sec = i & 3;
        uint32_t d = st + r * 80 + sec * 16;
        size_t ga = (size_t)(mb * 128 + r) * DIM + ch * 32 + sec * 8;
        size_t gb = (size_t)(nb * 128 + r) * DIM + ch * 32 + sec * 8;
        CP_ASYNC16(d,                 Ah + ga);
        CP_ASYNC16(d + MAT_BYTES,     Al + ga);
        CP_ASYNC16(d + 2 * MAT_BYTES, Bh + gb);
        CP_ASYNC16(d + 3 * MAT_BYTES, Bl + gb);
    }
}

__device__ __forceinline__ void mm_tile(const __nv_bfloat16* __restrict__ Ah,
                                        const __nv_bfloat16* __restrict__ Al,
                                        const __nv_bfloat16* __restrict__ Bh,
                                        const __nv_bfloat16* __restrict__ Bl,
                                        float* __restrict__ Cf,
                                        const float* __restrict__ bias,
                                        __nv_bfloat16* __restrict__ Dh,
                                        __nv_bfloat16* __restrict__ Dl,
                                        int mode, float scale)
{
    extern __shared__ char smem[];
    const uint32_t sb = smem_u32(smem);
    const int tid  = threadIdx.x;
    const int wid  = tid >> 5;
    const int lane = tid & 31;
    const int wm   = wid & 1;
    const int wn   = wid >> 1;
    const int mb   = blockIdx.y;
    const int nb   = blockIdx.x;

    const int r4 = lane >> 2;
    const int kq = (lane & 3) * 2;

    float acc[4][4][4];
#pragma unroll
    for (int fm = 0; fm < 4; fm++)
#pragma unroll
        for (int fn = 0; fn < 4; fn++)
#pragma unroll
            for (int q = 0; q < 4; q++) acc[fm][fn][q] = 0.0f;

    mm_load_chunk(sb, 0, 0, Ah, Al, Bh, Bl, mb, nb, tid);
    CP_COMMIT();

#pragma unroll 1
    for (int ch = 0; ch < 32; ch++) {
        if (ch + 1 < 32) {
            mm_load_chunk(sb, (ch + 1) & 1, ch + 1, Ah, Al, Bh, Bl, mb, nb, tid);
            CP_COMMIT();
            CP_WAIT1();
        } else {
            CP_WAIT0();
        }
        __syncthreads();

        const char* stg = smem + (ch & 1) * STAGE_BYTES;
        const char* aB  = stg + (wm * 64) * 80;
        const char* bB  = stg + 2 * MAT_BYTES + (wn * 32) * 80;

#pragma unroll
        for (int ks = 0; ks < 2; ks++) {
            const int kb = (ks * 16 + kq) * 2;
            uint32_t bh[4][2], bl[4][2];
#pragma unroll
            for (int fn = 0; fn < 4; fn++) {
                const char* p = bB + (fn * 8 + r4) * 80 + kb;
                bh[fn][0] = *(const uint32_t*)p;
                bh[fn][1] = *(const uint32_t*)(p + 16);
                bl[fn][0] = *(const uint32_t*)(p + MAT_BYTES);
                bl[fn][1] = *(const uint32_t*)(p + MAT_BYTES + 16);
            }
#pragma unroll
            for (int fm = 0; fm < 4; fm++) {
                const char* p = aB + (fm * 16 + r4) * 80 + kb;
                uint32_t ah0 = *(const uint32_t*)p;
                uint32_t ah1 = *(const uint32_t*)(p + 8 * 80);
                uint32_t ah2 = *(const uint32_t*)(p + 16);
                uint32_t ah3 = *(const uint32_t*)(p + 8 * 80 + 16);
                uint32_t al0 = *(const uint32_t*)(p + MAT_BYTES);
                uint32_t al1 = *(const uint32_t*)(p + MAT_BYTES + 8 * 80);
                uint32_t al2 = *(const uint32_t*)(p + MAT_BYTES + 16);
                uint32_t al3 = *(const uint32_t*)(p + MAT_BYTES + 8 * 80 + 16);
#pragma unroll
                for (int fn = 0; fn < 4; fn++) {
                    mma16816(acc[fm][fn], ah0, ah1, ah2, ah3, bh[fn][0], bh[fn][1]);
                    mma16816(acc[fm][fn], ah0, ah1, ah2, ah3, bl[fn][0], bl[fn][1]);
                    mma16816(acc[fm][fn], al0, al1, al2, al3, bh[fn][0], bh[fn][1]);
                }
            }
        }
        __syncthreads();
    }

    // epilogue
#pragma unroll
    for (int fm = 0; fm < 4; fm++) {
        const int row = mb * 128 + wm * 64 + fm * 16 + r4;
#pragma unroll
        for (int fn = 0; fn < 4; fn++) {
            const int col = nb * 128 + wn * 32 + fn * 8 + kq;
            float v0 = acc[fm][fn][0], v1 = acc[fm][fn][1];
            float v2 = acc[fm][fn][2], v3 = acc[fm][fn][3];
            if (mode == 0) {
                float b0 = bias ? bias[col] : 0.f, b1 = bias ? bias[col + 1] : 0.f;
                *(float2*)&Cf[(size_t)row * DIM + col] = make_float2(v0 + b0, v1 + b1);
                *(float2*)&Cf[(size_t)(row + 8) * DIM + col] = make_float2(v2 + b0, v3 + b1);
            } else if (mode == 1) {
                uint32_t hi, lo;
                split2(v0 * scale, v1 * scale, hi, lo);
                *(uint32_t*)&Dh[(size_t)row * DIM + col] = hi;
                *(uint32_t*)&Dl[(size_t)row * DIM + col] = lo;
                split2(v2 * scale, v3 * scale, hi, lo);
                *(uint32_t*)&Dh[(size_t)(row + 8) * DIM + col] = hi;
                *(uint32_t*)&Dl[(size_t)(row + 8) * DIM + col] = lo;
            } else {
                __nv_bfloat16 h, l;
                h = __float2bfloat16(v0); l = __float2bfloat16(v0 - __bfloat162float(h));
                Dh[(size_t)col * SEQ + row] = h;       Dl[(size_t)col * SEQ + row] = l;
                h = __float2bfloat16(v1); l = __float2bfloat16(v1 - __bfloat162float(h));
                Dh[(size_t)(col + 1) * SEQ + row] = h; Dl[(size_t)(col + 1) * SEQ + row] = l;
                h = __float2bfloat16(v2); l = __float2bfloat16(v2 - __bfloat162float(h));
                Dh[(size_t)col * SEQ + row + 8] = h;   Dl[(size_t)col * SEQ + row + 8] = l;
                h = __float2bfloat16(v3); l = __float2bfloat16(v3 - __bfloat162float(h));
                Dh[(size_t)(col + 1) * SEQ + row + 8] = h; Dl[(size_t)(col + 1) * SEQ + row + 8] = l;
            }
        }
    }
}

__global__ __launch_bounds__(256) void mm_qkv_kernel()
{
    if (blockIdx.z == 0)
        mm_tile(g_xh, g_xl, g_Wqh, g_Wql, nullptr, nullptr, g_Qh, g_Ql, 1, 0.125f);
    else if (blockIdx.z == 1)
        mm_tile(g_xh, g_xl, g_Wkh, g_Wkl, nullptr, nullptr, g_Kh, g_Kl, 1, 1.0f);
    else
        mm_tile(g_xh, g_xl, g_Wvh, g_Wvl, nullptr, nullptr, g_Vth, g_Vtl, 2, 1.0f);
}

__global__ __launch_bounds__(256) void mm_out_kernel(const float* __restrict__ bo,
                                                     float* __restrict__ out)
{
    mm_tile(g_ch, g_cl, g_Woh, g_Wol, out, bo, nullptr, nullptr, 0, 1.0f);
}

// ---------------------------------------------------------------------------
// Flash attention (round-9 body verbatim; LPT grid mapping).
// S = QK^T bf16 3-term; PV bf16 3-term. Q frags register-resident.
// Grid: 512 CTAs, idx -> (qb = 31 - idx/16, h = idx%16) so the longest
// blocks across ALL heads launch first (LPT scheduling).
// ---------------------------------------------------------------------------
#define KSTRIDE_B 144
#define VSTRIDE_B 272
#define KBYTES   (128 * KSTRIDE_B)            // 18432
#define VBYTES   (64 * VSTRIDE_B)             // 17408
#define STAGE_A  (2 * KBYTES + 2 * VBYTES)    // 71680
#define ATTN_SMEM (2 * STAGE_A)               // 143360

__global__ __launch_bounds__(256, 1) void attn_kernel()
{
    extern __shared__ char smem[];
    const uint32_t sb = smem_u32(smem);
    const int tid  = threadIdx.x;
    const int wid  = tid >> 5;
    const int lane = tid & 31;
    const int r4   = lane >> 2;
    const int kq   = (lane & 3) * 2;
    const int qb   = 31 - (blockIdx.x >> 4);   // LPT: longest q-blocks first
    const int h    = blockIdx.x & 15;
    const int hc   = h * HD;

    const int R0 = qb * 128 + wid * 16 + r4;
    const int R1 = R0 + 8;

    uint32_t qh[4][4], ql[4][4];
#pragma unroll
    for (int ks = 0; ks < 4; ks++) {
        const size_t k0 = (size_t)hc + ks * 16 + kq;
        qh[ks][0] = *(const uint32_t*)&g_Qh[(size_t)R0 * DIM + k0];
        qh[ks][1] = *(const uint32_t*)&g_Qh[(size_t)R1 * DIM + k0];
        qh[ks][2] = *(const uint32_t*)&g_Qh[(size_t)R0 * DIM + k0 + 8];
        qh[ks][3] = *(const uint32_t*)&g_Qh[(size_t)R1 * DIM + k0 + 8];
        ql[ks][0] = *(const uint32_t*)&g_Ql[(size_t)R0 * DIM + k0];
        ql[ks][1] = *(const uint32_t*)&g_Ql[(size_t)R1 * DIM + k0];
        ql[ks][2] = *(const uint32_t*)&g_Ql[(size_t)R0 * DIM + k0 + 8];
        ql[ks][3] = *(const uint32_t*)&g_Ql[(size_t)R1 * DIM + k0 + 8];
    }

    float o[8][4];
#pragma unroll
    for (int i = 0; i < 8; i++)
#pragma unroll
        for (int j = 0; j < 4; j++) o[i][j] = 0.0f;
    float m0 = -1e30f, m1 = -1e30f, l0 = 0.0f, l1 = 0.0f;

    auto load_stage = [&](int stg, int kb) {
        const uint32_t st = sb + stg * STAGE_A;
#pragma unroll
        for (int it = 0; it < 4; it++) {
            int i = tid + it * 256;
            int r = i >> 3, sec = i & 7;
            uint32_t d = st + r * KSTRIDE_B + sec * 16;
            size_t g = (size_t)(kb * 128 + r) * DIM + hc + sec * 8;
            CP_ASYNC16(d, g_Kh + g);
            CP_ASYNC16(d + KBYTES, g_Kl + g);
        }
        const uint32_t vst = st + 2 * KBYTES;
#pragma unroll
        for (int it = 0; it < 4; it++) {
            int i = tid + it * 256;
            int dd = i >> 4, sec = i & 15;
            uint32_t d = vst + dd * VSTRIDE_B + sec * 16;
            size_t g = (size_t)(hc + dd) * SEQ + kb * 128 + sec * 8;
            CP_ASYNC16(d, g_Vth + g);
            CP_ASYNC16(d + VBYTES, g_Vtl + g);
        }
    };

    load_stage(0, 0);
    CP_COMMIT();

#pragma unroll 1
    for (int kb = 0; kb <= qb; kb++) {
        if (kb < qb) { load_stage((kb + 1) & 1, kb + 1); CP_COMMIT(); CP_WAIT1(); }
        else         { CP_WAIT0(); }
        __syncthreads();

        const char* kbase = smem + (kb & 1) * STAGE_A;
        const char* vbase = kbase + 2 * KBYTES;

        float s[16][4];
#pragma unroll
        for (int nf = 0; nf < 16; nf++) {
#pragma unroll
            for (int q = 0; q < 4; q++) s[nf][q] = 0.0f;
#pragma unroll
            for (int ks = 0; ks < 4; ks++) {
                const char* p = kbase + (nf * 8 + r4) * KSTRIDE_B + (ks * 16 + kq) * 2;
                uint32_t bh0 = *(const uint32_t*)p;
                uint32_t bh1 = *(const uint32_t*)(p + 16);
                uint32_t bl0 = *(const uint32_t*)(p + KBYTES);
                uint32_t bl1 = *(const uint32_t*)(p + KBYTES + 16);
                mma16816(s[nf], qh[ks][0], qh[ks][1], qh[ks][2], qh[ks][3], bh0, bh1);
                mma16816(s[nf], qh[ks][0], qh[ks][1], qh[ks][2], qh[ks][3], bl0, bl1);
                mma16816(s[nf], ql[ks][0], ql[ks][1], ql[ks][2], ql[ks][3], bh0, bh1);
            }
        }

        if (kb == qb) {
#pragma unroll
            for (int nf = 0; nf < 16; nf++) {
                int C0 = kb * 128 + nf * 8 + kq;
                if (C0 > R0)     s[nf][0] = -1e30f;
                if (C0 + 1 > R0) s[nf][1] = -1e30f;
                if (C0 > R1)     s[nf][2] = -1e30f;
                if (C0 + 1 > R1) s[nf][3] = -1e30f;
            }
        }

        {
            float mx0 = m0, mx1 = m1;
#pragma unroll
            for (int nf = 0; nf < 16; nf++) {
                mx0 = fmaxf(mx0, fmaxf(s[nf][0], s[nf][1]));
                mx1 = fmaxf(mx1, fmaxf(s[nf][2], s[nf][3]));
            }
            mx0 = fmaxf(mx0, __shfl_xor_sync(0xffffffffu, mx0, 1));
            mx0 = fmaxf(mx0, __shfl_xor_sync(0xffffffffu, mx0, 2));
            mx1 = fmaxf(mx1, __shfl_xor_sync(0xffffffffu, mx1, 1));
            mx1 = fmaxf(mx1, __shfl_xor_sync(0xffffffffu, mx1, 2));
            float fac0 = __expf(m0 - mx0);
            float fac1 = __expf(m1 - mx1);
            m0 = mx0; m1 = mx1;
            float sum0 = 0.f, sum1 = 0.f;
#pragma unroll
            for (int nf = 0; nf < 16; nf++) {
                s[nf][0] = __expf(s[nf][0] - mx0);
                s[nf][1] = __expf(s[nf][1] - mx0);
                s[nf][2] = __expf(s[nf][2] - mx1);
                s[nf][3] = __expf(s[nf][3] - mx1);
                sum0 += s[nf][0] + s[nf][1];
                sum1 += s[nf][2] + s[nf][3];
            }
            sum0 += __shfl_xor_sync(0xffffffffu, sum0, 1);
            sum0 += __shfl_xor_sync(0xffffffffu, sum0, 2);
            sum1 += __shfl_xor_sync(0xffffffffu, sum1, 1);
            sum1 += __shfl_xor_sync(0xffffffffu, sum1, 2);
            l0 = l0 * fac0 + sum0;
            l1 = l1 * fac1 + sum1;
#pragma unroll
            for (int i = 0; i < 8; i++) {
                o[i][0] *= fac0; o[i][1] *= fac0;
                o[i][2] *= fac1; o[i][3] *= fac1;
            }
        }

#pragma unroll
        for (int kk = 0; kk < 8; kk++) {
            uint32_t ph[4], pl[4];
            split2(s[2 * kk][0],     s[2 * kk][1],     ph[0], pl[0]);
            split2(s[2 * kk][2],     s[2 * kk][3],     ph[1], pl[1]);
            split2(s[2 * kk + 1][0], s[2 * kk + 1][1], ph[2], pl[2]);
            split2(s[2 * kk + 1][2], s[2 * kk + 1][3], ph[3], pl[3]);
#pragma unroll
            for (int onf = 0; onf < 8; onf++) {
                const char* p = vbase + (onf * 8 + r4) * VSTRIDE_B + (kk * 16 + kq) * 2;
                uint32_t bh0 = *(const uint32_t*)p;
                uint32_t bh1 = *(const uint32_t*)(p + 16);
                uint32_t bl0 = *(const uint32_t*)(p + VBYTES);
                uint32_t bl1 = *(const uint32_t*)(p + VBYTES + 16);
                mma16816(o[onf], ph[0], ph[1], ph[2], ph[3], bh0, bh1);
                mma16816(o[onf], ph[0], ph[1], ph[2], ph[3], bl0, bl1);
                mma16816(o[onf], pl[0], pl[1], pl[2], pl[3], bh0, bh1);
            }
        }
        __syncthreads();
    }

    const float i0 = 1.0f / l0;
    const float i1 = 1.0f / l1;
#pragma unroll
    for (int onf = 0; onf < 8; onf++) {
        uint32_t hi, lo;
        const size_t c0 = (size_t)hc + onf * 8 + kq;
        split2(o[onf][0] * i0, o[onf][1] * i0, hi, lo);
        *(uint32_t*)&g_ch[(size_t)R0 * DIM + c0] = hi;
        *(uint32_t*)&g_cl[(size_t)R0 * DIM + c0] = lo;
        split2(o[onf][2] * i1, o[onf][3] * i1, hi, lo);
        *(uint32_t*)&g_ch[(size_t)R1 * DIM + c0] = hi;
        *(uint32_t*)&g_cl[(size_t)R1 * DIM + c0] = lo;
    }
}

extern "C" void kernel_launch(void* const* d_in, const int* in_sizes, int n_in,
                              void* d_out, int out_size)
{
    (void)in_sizes; (void)n_in; (void)out_size;
    const float* x  = (const float*)d_in[0];
    const float* Wq = (const float*)d_in[1];
    const float* Wk = (const float*)d_in[2];
    const float* Wv = (const float*)d_in[3];
    const float* Wo = (const float*)d_in[4];
    const float* bo = (const float*)d_in[5];
    float* out = (float*)d_out;

    static bool attr_set = false;
    if (!attr_set) {
        cudaFuncSetAttribute(attn_kernel,
                             cudaFuncAttributeMaxDynamicSharedMemorySize, ATTN_SMEM);
        cudaFuncSetAttribute(mm_qkv_kernel,
                             cudaFuncAttributeMaxDynamicSharedMemorySize, MM_SMEM);
        cudaFuncSetAttribute(mm_out_kernel,
                             cudaFuncAttributeMaxDynamicSharedMemorySize, MM_SMEM);
        attr_set = true;
    }

    // 1) single fused conversion pass (x + 4 weights -> bf16 split)
    convert_all_kernel<<<(SEQ + 4 * DIM) * 128 / 256, 256>>>(x, Wq, Wk, Wv, Wo);

    // 2) Q/K/V projections (split-bf16 epilogues; Q scaled, V transposed)
    {
        dim3 grid(DIM / 128, SEQ / 128, 3);
        mm_qkv_kernel<<<grid, 256, MM_SMEM>>>();
    }
    // 3) causal flash attention (bf16 3-term, LPT-ordered 1-D grid)
    attn_kernel<<<SEQ / 128 * NH, 256, ATTN_SMEM>>>();
    // 4) output projection + bias
    {
        dim3 grid(DIM / 128, SEQ / 128, 1);
        mm_out_kernel<<<grid, 256, MM_SMEM>>>(bo, out);
    }
}